// round 13
// baseline (speedup 1.0000x reference)
#include <cuda_runtime.h>
#include <cstdint>

__constant__ int c_starts[17] = {0, 4, 6, 8, 12, 16, 19, 22, 24, 28, 30, 36, 38, 41, 44, 47, 50};

#define MAX_BC 4096
__device__ unsigned g_inter[MAX_BC];
__device__ unsigned g_pred[MAX_BC];
__device__ unsigned g_gt[MAX_BC];
__device__ unsigned g_done;   // zero-initialized; reset by last block each run
__device__ unsigned g_work;   // work-stealing cursor; reset by last block each run

constexpr int TPB_F    = 256;
constexpr int TILE_PTS = 1024;          // one float4 per thread per row

// Process one 1024-pt tile. Per-thread packed accumulators over 4 points;
// full warp reduce gives bin sums <= 4*32 = 128 << 1023 -> safe.
template <int W>
__device__ __forceinline__ void do_tile(const float* __restrict__ l0,
                                        const int* __restrict__ tb,
                                        float* __restrict__ pb,
                                        int start, int N, int gbase)
{
    const int tid = threadIdx.x;
    const int n = tid * 4;

    float4 best = __ldcs(reinterpret_cast<const float4*>(l0 + n));
    int bc0 = 0, bc1 = 0, bc2 = 0, bc3 = 0;
#pragma unroll
    for (int j = 1; j < W; ++j) {
        const float4 v = __ldcs(reinterpret_cast<const float4*>(l0 + (size_t)j * N + n));
        if (v.x > best.x) { best.x = v.x; bc0 = j; }   // strict > keeps first index on ties
        if (v.y > best.y) { best.y = v.y; bc1 = j; }
        if (v.z > best.z) { best.z = v.z; bc2 = j; }
        if (v.w > best.w) { best.w = v.w; bc3 = j; }
    }
    const int4 t4 = __ldcs(reinterpret_cast<const int4*>(tb + n));

    unsigned long long acc_p = 0ull, acc_i = 0ull, acc_g = 0ull;
    const int bcs[4] = {bc0, bc1, bc2, bc3};
    const int tg[4]  = {t4.x, t4.y, t4.z, t4.w};
#pragma unroll
    for (int e = 0; e < 4; ++e) {
        const unsigned bt = (unsigned)(tg[e] - start);
        const unsigned long long one = 1ull << (bcs[e] * 10);
        acc_p += one;
        if (bt == (unsigned)bcs[e]) acc_i += one;            // intersection
        if (bt < (unsigned)W) acc_g += 1ull << (bt * 10);    // in-range gt
        pb[n + e] = (float)(bcs[e] + start);                 // pb may be 4B-offset
    }

    // full warp reduction (sums <= 128)
#pragma unroll
    for (int o = 16; o; o >>= 1) {
        acc_p += __shfl_down_sync(0xFFFFFFFFu, acc_p, o);
        acc_i += __shfl_down_sync(0xFFFFFFFFu, acc_i, o);
        acc_g += __shfl_down_sync(0xFFFFFFFFu, acc_g, o);
    }
    // lane j < W flushes bin j (broadcast from lane 0)
    const unsigned long long rp = __shfl_sync(0xFFFFFFFFu, acc_p, 0);
    const unsigned long long ri = __shfl_sync(0xFFFFFFFFu, acc_i, 0);
    const unsigned long long rg = __shfl_sync(0xFFFFFFFFu, acc_g, 0);
    const int lane = tid & 31;
    if (lane < W) {
        const unsigned cp = (unsigned)((rp >> (10 * lane)) & 1023u);
        const unsigned ci = (unsigned)((ri >> (10 * lane)) & 1023u);
        const unsigned cg = (unsigned)((rg >> (10 * lane)) & 1023u);
        if (cp) atomicAdd(&g_pred[gbase + lane], cp);
        if (ci) atomicAdd(&g_inter[gbase + lane], ci);
        if (cg) atomicAdd(&g_gt[gbase + lane], cg);
    }
}

__global__ void __launch_bounds__(TPB_F, 6)
seg_hist_steal(const float* __restrict__ logits,
               const int* __restrict__ targets,
               const int* __restrict__ labels,
               float* __restrict__ pred_out,
               float* __restrict__ mean_out,
               int C, int N, int B, int total_tiles, int tiles_per_b)
{
    __shared__ int s_next[2];
    const int tid = threadIdx.x;

    if (tid == 0) s_next[0] = (int)atomicAdd(&g_work, 1u);
    __syncthreads();

    for (int k = 0; ; ++k) {
        const int t = s_next[k & 1];
        if (tid == 0) s_next[(k + 1) & 1] = (int)atomicAdd(&g_work, 1u);  // pipelined steal
        if (t >= total_tiles) break;

        const int b = t / tiles_per_b;
        const int chunk = t - b * tiles_per_b;

        int cls = labels[b];
        cls = min(max(cls, 0), 15);
        const int start = c_starts[cls];
        const int width = c_starts[cls + 1] - start;

        const int n0 = chunk * TILE_PTS;
        const float* l0 = logits + ((size_t)b * C + start) * N + n0;
        const int* tb = targets + (size_t)b * N + n0;
        float* pb = pred_out + (size_t)b * N + n0;
        const int gbase = b * C + start;

        switch (width) {
            case 2: do_tile<2>(l0, tb, pb, start, N, gbase); break;
            case 3: do_tile<3>(l0, tb, pb, start, N, gbase); break;
            case 4: do_tile<4>(l0, tb, pb, start, N, gbase); break;
            default: do_tile<6>(l0, tb, pb, start, N, gbase); break;
        }
        __syncthreads();     // s_next[(k+1)&1] visible for next iteration
    }

    // ---- last-block finalize (fused tail) ----
    __shared__ unsigned s_last;
    if (tid == 0) {
        __threadfence();
        s_last = (atomicAdd(&g_done, 1u) == (unsigned)(gridDim.x - 1)) ? 1u : 0u;
    }
    __syncthreads();
    if (!s_last) return;

    __shared__ float s_iou[64];
    float v = 0.0f;
    if (tid < B) {
        int cl = labels[tid];
        cl = min(max(cl, 0), 15);
        const int st = c_starts[cl];
        const int wd = c_starts[cl + 1] - st;

        unsigned ci[6], cp[6], cg[6];
#pragma unroll
        for (int j = 0; j < 6; ++j) {
            const int g = tid * C + st + min(j, wd - 1);
            ci[j] = g_inter[g]; cp[j] = g_pred[g]; cg[j] = g_gt[g];
        }
        float acc = 0.0f;
#pragma unroll
        for (int j = 0; j < 6; ++j) {
            if (j < wd) {
                const float inter = (float)ci[j];
                const float uni = (float)cp[j] + (float)cg[j] - inter;
                acc += (uni == 0.0f) ? 1.0f : (inter / fmaxf(uni, 1.0f));
            }
        }
        v = acc / (float)wd;
#pragma unroll
        for (int j = 0; j < 6; ++j) {
            if (j < wd) {
                const int g = tid * C + st + j;
                g_inter[g] = 0u; g_pred[g] = 0u; g_gt[g] = 0u;   // reset for next replay
            }
        }
    }
    if (tid < 64) s_iou[tid] = v;
    __syncthreads();
    if (tid == 0) {
        float total = 0.0f;
        for (int i = 0; i < B; i++) total += s_iou[i];
        if (mean_out) *mean_out = total / (float)B;
        g_done = 0u;
        g_work = 0u;                                            // reset cursor for next replay
        __threadfence();
    }
}

// ---------------- fallback (generic sizes): separate kernels ----------------
template <int TPB>
__global__ void __launch_bounds__(TPB)
seg_hist_generic(const float* __restrict__ logits,
                 const int* __restrict__ targets,
                 const int* __restrict__ labels,
                 float* __restrict__ pred_out,
                 int C, int N)
{
    const int b = blockIdx.y;
    int cls = labels[b];
    cls = min(max(cls, 0), 15);
    const int start = c_starts[cls];
    const int width = c_starts[cls + 1] - start;

    __shared__ unsigned s_pred[8], s_gt[8], s_inter[8];
    if (threadIdx.x < 8) { s_pred[threadIdx.x] = 0u; s_gt[threadIdx.x] = 0u; s_inter[threadIdx.x] = 0u; }
    __syncthreads();

    const float* lb = logits + (size_t)b * C * N;
    const int* tb = targets + (size_t)b * N;
    float* pb = pred_out + (size_t)b * N;

    const int pts = (N + gridDim.x - 1) / gridDim.x;
    const int n0 = blockIdx.x * pts;
    const int n1 = min(n0 + pts, N);

    for (int n = n0 + threadIdx.x; n < n1; n += TPB) {
        float best = lb[(size_t)start * N + n];
        int bestc = 0;
        for (int j = 1; j < width; j++) {
            float v = lb[(size_t)(start + j) * N + n];
            if (v > best) { best = v; bestc = j; }
        }
        const unsigned bt = (unsigned)(tb[n] - start);
        atomicAdd(&s_pred[bestc], 1u);
        if (bt == (unsigned)bestc) atomicAdd(&s_inter[bestc], 1u);
        if (bt < (unsigned)width) atomicAdd(&s_gt[bt], 1u);
        pb[n] = (float)(bestc + start);
    }
    __syncthreads();
    if (threadIdx.x < width) {
        const int g = b * C + start + threadIdx.x;
        if (s_pred[threadIdx.x])  atomicAdd(&g_pred[g],  s_pred[threadIdx.x]);
        if (s_gt[threadIdx.x])    atomicAdd(&g_gt[g],    s_gt[threadIdx.x]);
        if (s_inter[threadIdx.x]) atomicAdd(&g_inter[g], s_inter[threadIdx.x]);
    }
}

__global__ void finalize_kernel(const int* __restrict__ labels,
                                float* __restrict__ mean_out,
                                int B, int C)
{
    __shared__ float s_iou[128];
    const int b = threadIdx.x;
    float v = 0.0f;
    if (b < B) {
        int cls = labels[b];
        cls = min(max(cls, 0), 15);
        const int start = c_starts[cls];
        const int end = c_starts[cls + 1];
        float acc = 0.0f;
        for (int p = start; p < end; p++) {
            const int g = b * C + p;
            const float inter = (float)g_inter[g];
            const float uni = (float)g_pred[g] + (float)g_gt[g] - inter;
            const float iou = (uni == 0.0f) ? 1.0f : (inter / fmaxf(uni, 1.0f));
            acc += iou;
            g_inter[g] = 0u; g_pred[g] = 0u; g_gt[g] = 0u;
        }
        v = acc / (float)(end - start);
    }
    if (b < 128) s_iou[b] = v;
    __syncthreads();
    if (threadIdx.x == 0) {
        float total = 0.0f;
        for (int i = 0; i < B; i++) total += s_iou[i];
        if (mean_out) *mean_out = total / (float)B;
    }
}

extern "C" void kernel_launch(void* const* d_in, const int* in_sizes, int n_in,
                              void* d_out, int out_size)
{
    // Identify inputs by element count (labels: B, targets: B*N, logits: B*C*N)
    int i_log = 0, i_lab = 0;
    for (int i = 0; i < 3; i++) {
        if (in_sizes[i] > in_sizes[i_log]) i_log = i;
        if (in_sizes[i] < in_sizes[i_lab]) i_lab = i;
    }
    const int i_tgt = 3 - i_log - i_lab;

    const float* logits  = (const float*)d_in[i_log];
    const int*   targets = (const int*)d_in[i_tgt];
    const int*   labels  = (const int*)d_in[i_lab];

    const int B  = in_sizes[i_lab];
    const int BN = in_sizes[i_tgt];
    const int N  = BN / B;
    const int C  = in_sizes[i_log] / BN;

    float* out = (float*)d_out;
    float* mean_out = nullptr;
    float* pred_out = nullptr;
    if (out_size >= BN + 1)      { mean_out = out; pred_out = out + 1; }
    else if (out_size == BN)     { pred_out = out; }
    else                         { mean_out = out; pred_out = out; }

    if (pred_out && (N % TILE_PTS) == 0 && B <= 64 && B * C <= MAX_BC) {
        const int tiles_per_b = N / TILE_PTS;
        const int total_tiles = B * tiles_per_b;           // 4096 for B=64, N=65536
        const int nblocks = 1024;
        seg_hist_steal<<<nblocks, TPB_F>>>(logits, targets, labels, pred_out,
                                           mean_out, C, N, B, total_tiles, tiles_per_b);
    } else {
        dim3 grid(32, B);
        seg_hist_generic<256><<<grid, 256>>>(logits, targets, labels, pred_out, C, N);
        finalize_kernel<<<1, 128>>>(labels, mean_out, B, C);
    }
}

// round 14
// speedup vs baseline: 1.1115x; 1.1115x over previous
#include <cuda_runtime.h>
#include <cstdint>

__constant__ int c_starts[17] = {0, 4, 6, 8, 12, 16, 19, 22, 24, 28, 30, 36, 38, 41, 44, 47, 50};

#define MAX_BC 4096
__device__ unsigned g_inter[MAX_BC];
__device__ unsigned g_pred[MAX_BC];
__device__ unsigned g_gt[MAX_BC];
__device__ unsigned g_done;   // zero-initialized; reset by last block each run

constexpr int TPB_F = 256;
constexpr int ITERS = 4;
constexpr int PTS   = TPB_F * 4;          // 1024 points per iteration
constexpr int SPAN  = PTS * ITERS;        // 4096 points per block

// Packed 64-bit accumulators: 6 bins x 10 bits; 16 pts/thread -> warp bin sums <= 512 < 1023.
template <int W>
__device__ __forceinline__ void fast_body(const float* __restrict__ l0,
                                          const int* __restrict__ tb,
                                          float* __restrict__ pb0,   // pb + n0 (phase a0 vs 16B)
                                          int start, int N, int b, int C, int a0,
                                          unsigned* s_pred, unsigned* s_inter, unsigned* s_gt)
{
    const int tid = threadIdx.x;
    const int lane = tid & 31;
    const unsigned FULL = 0xFFFFFFFFu;

    unsigned long long acc_p = 0ull, acc_i = 0ull, acc_g = 0ull;

#pragma unroll
    for (int it = 0; it < ITERS; ++it) {
        const int nt = it * PTS + tid * 4;          // tile-relative point of this thread

        float4 best = __ldcs(reinterpret_cast<const float4*>(l0 + nt));
        int bc0 = 0, bc1 = 0, bc2 = 0, bc3 = 0;
#pragma unroll
        for (int j = 1; j < W; ++j) {
            const float4 v = __ldcs(reinterpret_cast<const float4*>(l0 + (size_t)j * N + nt));
            if (v.x > best.x) { best.x = v.x; bc0 = j; }   // strict > keeps first index on ties
            if (v.y > best.y) { best.y = v.y; bc1 = j; }
            if (v.z > best.z) { best.z = v.z; bc2 = j; }
            if (v.w > best.w) { best.w = v.w; bc3 = j; }
        }
        const int4 t4 = __ldcs(reinterpret_cast<const int4*>(tb + nt));

        const int bcs[4] = {bc0, bc1, bc2, bc3};
        const int tg[4]  = {t4.x, t4.y, t4.z, t4.w};
#pragma unroll
        for (int e = 0; e < 4; ++e) {
            const unsigned bt = (unsigned)(tg[e] - start);
            const unsigned long long one = 1ull << (bcs[e] * 10);
            acc_p += one;
            if (bt == (unsigned)bcs[e]) acc_i += one;            // intersection
            if (bt < (unsigned)W) acc_g += 1ull << (bt * 10);    // in-range gt
        }

        // ---- aligned pred store via register-shuffle phase fix ----
        const float pf0 = (float)(bc0 + start), pf1 = (float)(bc1 + start);
        const float pf2 = (float)(bc2 + start), pf3 = (float)(bc3 + start);
        float* gp = pb0 + it * PTS + (tid >> 5) * 128;        // warp's 128-pt region

        if (a0 == 0) {
            *reinterpret_cast<float4*>(gp + 4 * lane) = make_float4(pf0, pf1, pf2, pf3);
        } else {
            // r_e = pf[(a0+e)&3]  (a0 is block-uniform)
            const float r0 = (a0 == 1) ? pf1 : (a0 == 2) ? pf2 : pf3;
            const float r1 = (a0 == 1) ? pf2 : (a0 == 2) ? pf3 : pf0;
            const float r2 = (a0 == 1) ? pf3 : (a0 == 2) ? pf0 : pf1;
            const float r3 = (a0 == 1) ? pf0 : (a0 == 2) ? pf1 : pf2;
            const float s0 = __shfl_down_sync(FULL, r0, 1);
            const float s1 = __shfl_down_sync(FULL, r1, 1);
            const float s2 = __shfl_down_sync(FULL, r2, 1);
            const float s3 = __shfl_down_sync(FULL, r3, 1);
            // v_e = (e < 4-a0) ? r_e : s_e
            const float v0 = (0 < 4 - a0) ? r0 : s0;
            const float v1 = (1 < 4 - a0) ? r1 : s1;
            const float v2 = (2 < 4 - a0) ? r2 : s2;
            const float v3 = (3 < 4 - a0) ? r3 : s3;
            if (lane < 31)
                *reinterpret_cast<float4*>(gp + 4 * lane + a0) = make_float4(v0, v1, v2, v3);
            if (lane == 0) {                      // head a0 points of the warp region
                gp[0] = pf0;
                if (a0 > 1) gp[1] = pf1;
                if (a0 > 2) gp[2] = pf2;
            }
            if (lane == 31) {                     // tail (4-a0) points
                gp[127] = pf3;
                if (a0 <= 2) gp[126] = pf2;
                if (a0 <= 1) gp[125] = pf1;
            }
        }
    }

    // full warp reduction of packed accumulators (sums <= 512)
#pragma unroll
    for (int o = 16; o; o >>= 1) {
        acc_p += __shfl_down_sync(0xFFFFFFFFu, acc_p, o);
        acc_i += __shfl_down_sync(0xFFFFFFFFu, acc_i, o);
        acc_g += __shfl_down_sync(0xFFFFFFFFu, acc_g, o);
    }
    if (lane == 0) {
#pragma unroll
        for (int j = 0; j < W; ++j) {
            const unsigned cp = (unsigned)((acc_p >> (10 * j)) & 1023u);
            const unsigned ci = (unsigned)((acc_i >> (10 * j)) & 1023u);
            const unsigned cg = (unsigned)((acc_g >> (10 * j)) & 1023u);
            if (cp) atomicAdd(&s_pred[j], cp);
            if (ci) atomicAdd(&s_inter[j], ci);
            if (cg) atomicAdd(&s_gt[j], cg);
        }
    }
    __syncthreads();
    if (tid < W) {
        const int g = b * C + start + tid;
        const unsigned sp = s_pred[tid], si = s_inter[tid], sg = s_gt[tid];
        if (sp) atomicAdd(&g_pred[g], sp);
        if (si) atomicAdd(&g_inter[g], si);
        if (sg) atomicAdd(&g_gt[g], sg);
    }
}

__global__ void __launch_bounds__(TPB_F, 5)
seg_hist_fast(const float* __restrict__ logits,
              const int* __restrict__ targets,
              const int* __restrict__ labels,
              float* __restrict__ pred_out,
              float* __restrict__ mean_out,
              int C, int N, int B, int total_blocks, int a0)
{
    __shared__ unsigned s_pred[8], s_inter[8], s_gt[8];
    const int tid = threadIdx.x;
    if (tid < 8) { s_pred[tid] = 0u; s_inter[tid] = 0u; s_gt[tid] = 0u; }
    __syncthreads();

    const int b = blockIdx.y;
    int cls = labels[b];
    cls = min(max(cls, 0), 15);
    const int start = c_starts[cls];
    const int width = c_starts[cls + 1] - start;

    const int n0 = blockIdx.x * SPAN;
    const float* l0 = logits + ((size_t)b * C + start) * N + n0;
    const int* tb = targets + (size_t)b * N + n0;
    float* pb0 = pred_out + (size_t)b * N + n0;

    switch (width) {
        case 2: fast_body<2>(l0, tb, pb0, start, N, b, C, a0, s_pred, s_inter, s_gt); break;
        case 3: fast_body<3>(l0, tb, pb0, start, N, b, C, a0, s_pred, s_inter, s_gt); break;
        case 4: fast_body<4>(l0, tb, pb0, start, N, b, C, a0, s_pred, s_inter, s_gt); break;
        default: fast_body<6>(l0, tb, pb0, start, N, b, C, a0, s_pred, s_inter, s_gt); break;
    }

    // ---- last-block finalize (fused tail) ----
    __shared__ unsigned s_last;
    if (tid == 0) {
        __threadfence();
        s_last = (atomicAdd(&g_done, 1u) == (unsigned)(total_blocks - 1)) ? 1u : 0u;
    }
    __syncthreads();
    if (!s_last) return;

    __shared__ float s_iou[64];
    float v = 0.0f;
    if (tid < B) {
        int cl = labels[tid];
        cl = min(max(cl, 0), 15);
        const int st = c_starts[cl];
        const int wd = c_starts[cl + 1] - st;

        unsigned ci[6], cp[6], cg[6];
#pragma unroll
        for (int j = 0; j < 6; ++j) {
            const int g = tid * C + st + min(j, wd - 1);
            ci[j] = g_inter[g]; cp[j] = g_pred[g]; cg[j] = g_gt[g];
        }
        float acc = 0.0f;
#pragma unroll
        for (int j = 0; j < 6; ++j) {
            if (j < wd) {
                const float inter = (float)ci[j];
                const float uni = (float)cp[j] + (float)cg[j] - inter;
                acc += (uni == 0.0f) ? 1.0f : (inter / fmaxf(uni, 1.0f));
            }
        }
        v = acc / (float)wd;
#pragma unroll
        for (int j = 0; j < 6; ++j) {
            if (j < wd) {
                const int g = tid * C + st + j;
                g_inter[g] = 0u; g_pred[g] = 0u; g_gt[g] = 0u;   // reset for next replay
            }
        }
    }
    if (tid < 64) s_iou[tid] = v;
    __syncthreads();
    if (tid == 0) {
        float total = 0.0f;
        for (int i = 0; i < B; i++) total += s_iou[i];
        if (mean_out) *mean_out = total / (float)B;
        g_done = 0u;
        __threadfence();
    }
}

// ---------------- fallback (generic sizes): separate kernels ----------------
template <int TPB>
__global__ void __launch_bounds__(TPB)
seg_hist_generic(const float* __restrict__ logits,
                 const int* __restrict__ targets,
                 const int* __restrict__ labels,
                 float* __restrict__ pred_out,
                 int C, int N)
{
    const int b = blockIdx.y;
    int cls = labels[b];
    cls = min(max(cls, 0), 15);
    const int start = c_starts[cls];
    const int width = c_starts[cls + 1] - start;

    __shared__ unsigned s_pred[8], s_gt[8], s_inter[8];
    if (threadIdx.x < 8) { s_pred[threadIdx.x] = 0u; s_gt[threadIdx.x] = 0u; s_inter[threadIdx.x] = 0u; }
    __syncthreads();

    const float* lb = logits + (size_t)b * C * N;
    const int* tb = targets + (size_t)b * N;
    float* pb = pred_out + (size_t)b * N;

    const int pts = (N + gridDim.x - 1) / gridDim.x;
    const int n0 = blockIdx.x * pts;
    const int n1 = min(n0 + pts, N);

    for (int n = n0 + threadIdx.x; n < n1; n += TPB) {
        float best = lb[(size_t)start * N + n];
        int bestc = 0;
        for (int j = 1; j < width; j++) {
            float v = lb[(size_t)(start + j) * N + n];
            if (v > best) { best = v; bestc = j; }
        }
        const unsigned bt = (unsigned)(tb[n] - start);
        atomicAdd(&s_pred[bestc], 1u);
        if (bt == (unsigned)bestc) atomicAdd(&s_inter[bestc], 1u);
        if (bt < (unsigned)width) atomicAdd(&s_gt[bt], 1u);
        pb[n] = (float)(bestc + start);
    }
    __syncthreads();
    if (threadIdx.x < width) {
        const int g = b * C + start + threadIdx.x;
        if (s_pred[threadIdx.x])  atomicAdd(&g_pred[g],  s_pred[threadIdx.x]);
        if (s_gt[threadIdx.x])    atomicAdd(&g_gt[g],    s_gt[threadIdx.x]);
        if (s_inter[threadIdx.x]) atomicAdd(&g_inter[g], s_inter[threadIdx.x]);
    }
}

__global__ void finalize_kernel(const int* __restrict__ labels,
                                float* __restrict__ mean_out,
                                int B, int C)
{
    __shared__ float s_iou[128];
    const int b = threadIdx.x;
    float v = 0.0f;
    if (b < B) {
        int cls = labels[b];
        cls = min(max(cls, 0), 15);
        const int start = c_starts[cls];
        const int end = c_starts[cls + 1];
        float acc = 0.0f;
        for (int p = start; p < end; p++) {
            const int g = b * C + p;
            const float inter = (float)g_inter[g];
            const float uni = (float)g_pred[g] + (float)g_gt[g] - inter;
            const float iou = (uni == 0.0f) ? 1.0f : (inter / fmaxf(uni, 1.0f));
            acc += iou;
            g_inter[g] = 0u; g_pred[g] = 0u; g_gt[g] = 0u;
        }
        v = acc / (float)(end - start);
    }
    if (b < 128) s_iou[b] = v;
    __syncthreads();
    if (threadIdx.x == 0) {
        float total = 0.0f;
        for (int i = 0; i < B; i++) total += s_iou[i];
        if (mean_out) *mean_out = total / (float)B;
    }
}

extern "C" void kernel_launch(void* const* d_in, const int* in_sizes, int n_in,
                              void* d_out, int out_size)
{
    // Identify inputs by element count (labels: B, targets: B*N, logits: B*C*N)
    int i_log = 0, i_lab = 0;
    for (int i = 0; i < 3; i++) {
        if (in_sizes[i] > in_sizes[i_log]) i_log = i;
        if (in_sizes[i] < in_sizes[i_lab]) i_lab = i;
    }
    const int i_tgt = 3 - i_log - i_lab;

    const float* logits  = (const float*)d_in[i_log];
    const int*   targets = (const int*)d_in[i_tgt];
    const int*   labels  = (const int*)d_in[i_lab];

    const int B  = in_sizes[i_lab];
    const int BN = in_sizes[i_tgt];
    const int N  = BN / B;
    const int C  = in_sizes[i_log] / BN;

    float* out = (float*)d_out;
    float* mean_out = nullptr;
    float* pred_out = nullptr;
    if (out_size >= BN + 1)      { mean_out = out; pred_out = out + 1; }
    else if (out_size == BN)     { pred_out = out; }
    else                         { mean_out = out; pred_out = out; }

    // output phase: elements until pred_out is 16B-aligned (0..3)
    const int a0 = (int)(((16u - ((unsigned)(uintptr_t)pred_out & 15u)) >> 2) & 3u);

    if (pred_out && (N % SPAN) == 0 && (N % 128) == 0 && B <= 64 && B * C <= MAX_BC) {
        dim3 grid(N / SPAN, B);                    // (16, 64) -> 1024 blocks
        const int total_blocks = (N / SPAN) * B;
        seg_hist_fast<<<grid, TPB_F>>>(logits, targets, labels, pred_out,
                                       mean_out, C, N, B, total_blocks, a0);
    } else {
        dim3 grid(32, B);
        seg_hist_generic<256><<<grid, 256>>>(logits, targets, labels, pred_out, C, N);
        finalize_kernel<<<1, 128>>>(labels, mean_out, B, C);
    }
}